// round 2
// baseline (speedup 1.0000x reference)
#include <cuda_runtime.h>

#define R    4
#define NTH  256
#define SLOPE 0.0025f

struct Params { const float* p[27]; };

__device__ __forceinline__ float rr(float v) { return v >= 0.f ? v : SLOPE * v; }

// Shared-memory weight offsets (floats), cumulative over d_in[1..26]:
// W_in(64) b_in(8) W_h1(32) b_h1(4) W_h2(16) b_h2(4) W_h3(16) b_h3(4)
// W_h4(16) b_h4(4) W_h5(16) b_h5(4) W_enc(4) b_enc(1) W_h6(4) b_h6(4)
// W_h7(16) b_h7(4) W_h8(16) b_h8(4) W_h9(16) b_h9(4) W_h10(16) b_h10(4)
// W_dec(32) b_dec(8)  => total 321
#define O_W_IN   0
#define O_B_IN   64
#define O_W_H1   72
#define O_B_H1   104
#define O_W_H2   108
#define O_B_H2   124
#define O_W_H3   128
#define O_B_H3   144
#define O_W_H4   148
#define O_B_H4   164
#define O_W_H5   168
#define O_B_H5   184
#define O_W_EN   188
#define O_B_EN   192
#define O_W_H6   193
#define O_B_H6   197
#define O_W_H7   201
#define O_B_H7   217
#define O_W_H8   221
#define O_B_H8   237
#define O_W_H9   241
#define O_B_H9   257
#define O_W_HA   261
#define O_B_HA   277
#define O_W_DE   281
#define O_B_DE   313
#define S_TOTAL  321

// dst[r][j] = (act? rrelu:id)( b[j] + sum_i src[r][i] * W[i*FO+j] )
template<int FI, int FO, bool ACT>
__device__ __forceinline__ void linear(const float* __restrict__ s, int Woff, int boff,
                                       const float (&src)[R][8], float (&dst)[R][8]) {
#pragma unroll
    for (int j = 0; j < FO; j++) {
        float acc[R];
        float bb = s[boff + j];
#pragma unroll
        for (int r = 0; r < R; r++) acc[r] = bb;
#pragma unroll
        for (int i = 0; i < FI; i++) {
            float w = s[Woff + i * FO + j];
#pragma unroll
            for (int r = 0; r < R; r++) acc[r] = fmaf(src[r][i], w, acc[r]);
        }
#pragma unroll
        for (int r = 0; r < R; r++) dst[r][j] = ACT ? rr(acc[r]) : acc[r];
    }
}

// dst[r][j] += b[j] + sum_i src[r][i] * W[i*FO+j]   (residual add, no activation)
template<int FI, int FO>
__device__ __forceinline__ void linear_add(const float* __restrict__ s, int Woff, int boff,
                                           const float (&src)[R][8], float (&dst)[R][8]) {
#pragma unroll
    for (int j = 0; j < FO; j++) {
        float acc[R];
        float bb = s[boff + j];
#pragma unroll
        for (int r = 0; r < R; r++) acc[r] = bb;
#pragma unroll
        for (int i = 0; i < FI; i++) {
            float w = s[Woff + i * FO + j];
#pragma unroll
            for (int r = 0; r < R; r++) acc[r] = fmaf(src[r][i], w, acc[r]);
        }
#pragma unroll
        for (int r = 0; r < R; r++) dst[r][j] += acc[r];
    }
}

__global__ __launch_bounds__(NTH)
void ann_fused_kernel(Params P, float* __restrict__ out, int N) {
    __shared__ float s[S_TOTAL];

    // Cooperative weight load: d_in[1..26] -> shared, once per block.
    {
        const int sz[26] = {64,8,32,4,16,4,16,4,16,4,16,4,4,1,4,4,16,4,16,4,16,4,16,4,32,8};
        int off = 0;
        for (int k = 0; k < 26; k++) {
            const float* src = P.p[k + 1];
            for (int i = threadIdx.x; i < sz[k]; i += NTH) s[off + i] = src[i];
            off += sz[k];
        }
    }
    __syncthreads();

    const float* __restrict__ xin = P.p[0];

    long base = (long)blockIdx.x * (R * NTH) + threadIdx.x;

    float x[R][8];   // running activation (up to 8-wide)
    float t[R][8];   // scratch

    // ---- load x_in rows (two float4 each, fully coalesced per r-slice) ----
#pragma unroll
    for (int r = 0; r < R; r++) {
        long row = base + (long)r * NTH;
        if (row < N) {
            float4 a = *reinterpret_cast<const float4*>(xin + row * 8);
            float4 b = *reinterpret_cast<const float4*>(xin + row * 8 + 4);
            x[r][0] = a.x; x[r][1] = a.y; x[r][2] = a.z; x[r][3] = a.w;
            x[r][4] = b.x; x[r][5] = b.y; x[r][6] = b.z; x[r][7] = b.w;
        } else {
#pragma unroll
            for (int i = 0; i < 8; i++) x[r][i] = 0.f;
        }
    }

    // ---- encoder ----
    linear<8, 8, true >(s, O_W_IN, O_B_IN, x, t);   // t = rrelu(x @ W_in + b_in)
    linear<8, 4, false>(s, O_W_H1, O_B_H1, t, x);   // x = t @ W_h1 + b_h1

    linear<4, 4, true >(s, O_W_H2, O_B_H2, x, t);   // residual block 1
    linear_add<4, 4>   (s, O_W_H3, O_B_H3, t, x);

    linear<4, 4, true >(s, O_W_H4, O_B_H4, x, t);   // residual block 2
    linear_add<4, 4>   (s, O_W_H5, O_B_H5, t, x);

    linear<4, 1, true >(s, O_W_EN, O_B_EN, x, t);   // t[r][0] = x_encode

    // store x_encode
#pragma unroll
    for (int r = 0; r < R; r++) {
        long row = base + (long)r * NTH;
        if (row < N) out[row] = t[r][0];
    }

    // ---- decoder ----
    linear<1, 4, true >(s, O_W_H6, O_B_H6, t, x);   // x = rrelu(e @ W_h6 + b_h6)

    linear<4, 4, true >(s, O_W_H7, O_B_H7, x, t);   // residual block 3
    linear_add<4, 4>   (s, O_W_H8, O_B_H8, t, x);

    linear<4, 4, true >(s, O_W_H9, O_B_H9, x, t);   // residual block 4
    linear_add<4, 4>   (s, O_W_HA, O_B_HA, t, x);

    linear<4, 8, true >(s, O_W_DE, O_B_DE, x, t);   // t = x_decode (8-wide)

    // store x_decode (two float4 per row)
    float* __restrict__ dec = out + N;
#pragma unroll
    for (int r = 0; r < R; r++) {
        long row = base + (long)r * NTH;
        if (row < N) {
            float4 a = make_float4(t[r][0], t[r][1], t[r][2], t[r][3]);
            float4 b = make_float4(t[r][4], t[r][5], t[r][6], t[r][7]);
            *reinterpret_cast<float4*>(dec + row * 8)     = a;
            *reinterpret_cast<float4*>(dec + row * 8 + 4) = b;
        }
    }
}

extern "C" void kernel_launch(void* const* d_in, const int* in_sizes, int n_in,
                              void* d_out, int out_size) {
    Params P;
    for (int k = 0; k < 27; k++) P.p[k] = (const float*)d_in[k];
    int N = in_sizes[0] / 8;                 // 4194304 rows
    int rows_per_block = R * NTH;            // 1024
    int blocks = (N + rows_per_block - 1) / rows_per_block;
    ann_fused_kernel<<<blocks, NTH>>>(P, (float*)d_out, N);
}